// round 1
// baseline (speedup 1.0000x reference)
#include <cuda_runtime.h>

// LSTM: B x T x I -> last hidden -> FC.  I=4, H=8, O=1, T=512.
// Layout: 8 lanes per batch element; lane j owns hidden unit j and computes
// gate rows {i,f,g,o} x unit j. Weights fully register-resident.
// h broadcast via __shfl_sync(width=8).

#define T_SEQ 512
#define IDIM  4
#define HDIM  8

__device__ __forceinline__ float sigmoid_f(float x) {
    // 1 / (1 + e^-x): MUFU.EX2 + MUFU.RCP, ~1e-7 rel err
    float e = __expf(-x);
    return __fdividef(1.0f, 1.0f + e);
}

__device__ __forceinline__ float tanh_f(float x) {
    // (e^{2x}-1)/(e^{2x}+1), clamped to avoid inf/inf
    x = fminf(fmaxf(x, -15.0f), 15.0f);
    float e = __expf(2.0f * x);
    return __fdividef(e - 1.0f, e + 1.0f);
}

__global__ __launch_bounds__(256, 4)
void lstm_fused_kernel(const float* __restrict__ x,
                       const float* __restrict__ W_ih,
                       const float* __restrict__ W_hh,
                       const float* __restrict__ b_ih,
                       const float* __restrict__ b_hh,
                       const float* __restrict__ W_fc,
                       const float* __restrict__ b_fc,
                       float* __restrict__ out,
                       int B)
{
    const int tid = threadIdx.x;
    const int j   = tid & 7;                       // hidden unit owned by this lane
    int b = blockIdx.x * 32 + (tid >> 3);          // batch element
    const bool valid = (b < B);
    if (b >= B) b = B - 1;                         // clamp: keep whole warp alive for shuffles

    // ---- load per-lane weights into registers ----
    float wih[4][4];    // [gate][input]
    float whh[4][8];    // [gate][hidden]
    float bias[4];
#pragma unroll
    for (int g = 0; g < 4; ++g) {
        const int row = g * HDIM + j;
        const float4 wv = *reinterpret_cast<const float4*>(W_ih + row * IDIM);
        wih[g][0] = wv.x; wih[g][1] = wv.y; wih[g][2] = wv.z; wih[g][3] = wv.w;
#pragma unroll
        for (int k = 0; k < HDIM; ++k) whh[g][k] = W_hh[row * HDIM + k];
        bias[g] = b_ih[row] + b_hh[row];
    }

    const float4* __restrict__ xp =
        reinterpret_cast<const float4*>(x) + (size_t)b * T_SEQ;

    float h = 0.0f, c = 0.0f;
    float4 xv = xp[0];                              // software pipeline: prefetch t=0

#pragma unroll 2
    for (int t = 0; t < T_SEQ; ++t) {
        const float4 xc = xv;
        if (t + 1 < T_SEQ) xv = xp[t + 1];          // prefetch next step

        // input projection + bias (h-independent: overlaps with prev-step chain)
        float acc[4];
#pragma unroll
        for (int g = 0; g < 4; ++g) {
            float a = fmaf(wih[g][0], xc.x, bias[g]);
            a = fmaf(wih[g][1], xc.y, a);
            a = fmaf(wih[g][2], xc.z, a);
            acc[g] = fmaf(wih[g][3], xc.w, a);
        }

        // recurrent projection: gather h from the 8-lane group
#pragma unroll
        for (int k = 0; k < HDIM; ++k) {
            const float hk = __shfl_sync(0xffffffffu, h, k, 8);
#pragma unroll
            for (int g = 0; g < 4; ++g)
                acc[g] = fmaf(hk, whh[g][k], acc[g]);
        }

        const float ig = sigmoid_f(acc[0]);
        const float fg = sigmoid_f(acc[1]);
        const float gg = tanh_f   (acc[2]);
        const float og = sigmoid_f(acc[3]);

        c = fmaf(fg, c, ig * gg);
        h = og * tanh_f(c);
    }

    // ---- FC head: out[b] = sum_j h_j * W_fc[j] + b_fc ----
    float v = h * __ldg(W_fc + j);
    v += __shfl_xor_sync(0xffffffffu, v, 1, 8);
    v += __shfl_xor_sync(0xffffffffu, v, 2, 8);
    v += __shfl_xor_sync(0xffffffffu, v, 4, 8);

    if (valid && j == 0) out[b] = v + b_fc[0];
}

extern "C" void kernel_launch(void* const* d_in, const int* in_sizes, int n_in,
                              void* d_out, int out_size)
{
    const float* x    = (const float*)d_in[0];
    const float* W_ih = (const float*)d_in[1];
    const float* W_hh = (const float*)d_in[2];
    const float* b_ih = (const float*)d_in[3];
    const float* b_hh = (const float*)d_in[4];
    const float* W_fc = (const float*)d_in[5];
    const float* b_fc = (const float*)d_in[6];
    float* out = (float*)d_out;

    const int B = in_sizes[0] / (T_SEQ * IDIM);    // 8192 for this problem
    const int batches_per_block = 32;              // 256 threads / 8 lanes
    const int grid = (B + batches_per_block - 1) / batches_per_block;

    lstm_fused_kernel<<<grid, 256>>>(x, W_ih, W_hh, b_ih, b_hh, W_fc, b_fc, out, B);
}

// round 2
// speedup vs baseline: 1.3692x; 1.3692x over previous
#include <cuda_runtime.h>

// LSTM: B x T x I -> last hidden -> FC.  I=4, H=8, O=1, T=512.
// 8 lanes per batch element; lane j owns hidden unit j (all 4 gate rows).
// Round-2 changes vs round 1:
//   * tanh.approx.f32 HW activation (5 MUFU/step vs 10)
//   * packed fma.rn.f32x2 over gate pairs (i,f) and (g,o)
//   * 2 independent batch elements per thread (ILP; weights shared in regs)
//   * 32-thread blocks -> ~1024 blocks -> even wave across 148 SMs

#define T_SEQ 512
#define IDIM  4
#define HDIM  8

typedef unsigned long long u64;

__device__ __forceinline__ u64 pack2(float a, float b) {
    u64 r; asm("mov.b64 %0,{%1,%2};" : "=l"(r) : "f"(a), "f"(b)); return r;
}
__device__ __forceinline__ u64 dup2(float a) {
    u64 r; asm("mov.b64 %0,{%1,%1};" : "=l"(r) : "f"(a)); return r;
}
__device__ __forceinline__ float2 unpack2(u64 v) {
    float2 r; asm("mov.b64 {%0,%1},%2;" : "=f"(r.x), "=f"(r.y) : "l"(v)); return r;
}
__device__ __forceinline__ u64 fma2(u64 a, u64 b, u64 c) {
    u64 d; asm("fma.rn.f32x2 %0,%1,%2,%3;" : "=l"(d) : "l"(a), "l"(b), "l"(c)); return d;
}
__device__ __forceinline__ float tanh_fast(float x) {
    float y; asm("tanh.approx.f32 %0,%1;" : "=f"(y) : "f"(x)); return y;
}
__device__ __forceinline__ float sig_fast(float x) {
    return fmaf(0.5f, tanh_fast(0.5f * x), 0.5f);
}

__global__ __launch_bounds__(32)
void lstm_fused_kernel(const float* __restrict__ x,
                       const float* __restrict__ W_ih,
                       const float* __restrict__ W_hh,
                       const float* __restrict__ b_ih,
                       const float* __restrict__ b_hh,
                       const float* __restrict__ W_fc,
                       const float* __restrict__ b_fc,
                       float* __restrict__ out,
                       int B)
{
    const int tid  = threadIdx.x;
    const int j    = tid & 7;                               // hidden unit owned
    const int half = (B + 1) >> 1;                          // groups handle b and b+half
    int gid = blockIdx.x * 4 + (tid >> 3);                  // group id = batch b0

    const bool v0 = (gid < half);
    if (gid >= half) gid = half - 1;                        // clamp, keep warp converged
    const int b0 = gid;
    const int b1 = gid + half;
    const bool v1 = (b1 < B);
    const int b1c = v1 ? b1 : b0;

    // ---- per-lane weights in registers, packed over gate pairs (i,f) / (g,o) ----
    u64 wih01[IDIM], wih23[IDIM];      // input weights
    u64 whh01[HDIM], whh23[HDIM];      // recurrent weights
    u64 bias01, bias23;
    {
        const int r0 = 0 * HDIM + j, r1 = 1 * HDIM + j;
        const int r2 = 2 * HDIM + j, r3 = 3 * HDIM + j;
#pragma unroll
        for (int m = 0; m < IDIM; ++m) {
            wih01[m] = pack2(W_ih[r0 * IDIM + m], W_ih[r1 * IDIM + m]);
            wih23[m] = pack2(W_ih[r2 * IDIM + m], W_ih[r3 * IDIM + m]);
        }
#pragma unroll
        for (int k = 0; k < HDIM; ++k) {
            whh01[k] = pack2(W_hh[r0 * HDIM + k], W_hh[r1 * HDIM + k]);
            whh23[k] = pack2(W_hh[r2 * HDIM + k], W_hh[r3 * HDIM + k]);
        }
        bias01 = pack2(b_ih[r0] + b_hh[r0], b_ih[r1] + b_hh[r1]);
        bias23 = pack2(b_ih[r2] + b_hh[r2], b_ih[r3] + b_hh[r3]);
    }

    const float4* __restrict__ xp0 = reinterpret_cast<const float4*>(x) + (size_t)b0  * T_SEQ;
    const float4* __restrict__ xp1 = reinterpret_cast<const float4*>(x) + (size_t)b1c * T_SEQ;

    float hA = 0.0f, cA = 0.0f;        // batch b0 state
    float hB = 0.0f, cB = 0.0f;        // batch b1 state
    float4 xvA = xp0[0];
    float4 xvB = xp1[0];

#pragma unroll 1
    for (int t = 0; t < T_SEQ; ++t) {
        const float4 xcA = xvA;
        const float4 xcB = xvB;
        const int tn = (t + 1) & (T_SEQ - 1);               // wraps to 0 on last iter (harmless)
        xvA = xp0[tn];
        xvB = xp1[tn];

        // ---- input projection + bias (independent of h: overlaps prev chain) ----
        u64 aA01 = fma2(wih01[0], dup2(xcA.x), bias01);
        u64 aA23 = fma2(wih23[0], dup2(xcA.x), bias23);
        u64 aB01 = fma2(wih01[0], dup2(xcB.x), bias01);
        u64 aB23 = fma2(wih23[0], dup2(xcB.x), bias23);
        {
            u64 d;
            d = dup2(xcA.y); aA01 = fma2(wih01[1], d, aA01); aA23 = fma2(wih23[1], d, aA23);
            d = dup2(xcA.z); aA01 = fma2(wih01[2], d, aA01); aA23 = fma2(wih23[2], d, aA23);
            d = dup2(xcA.w); aA01 = fma2(wih01[3], d, aA01); aA23 = fma2(wih23[3], d, aA23);
            d = dup2(xcB.y); aB01 = fma2(wih01[1], d, aB01); aB23 = fma2(wih23[1], d, aB23);
            d = dup2(xcB.z); aB01 = fma2(wih01[2], d, aB01); aB23 = fma2(wih23[2], d, aB23);
            d = dup2(xcB.w); aB01 = fma2(wih01[3], d, aB01); aB23 = fma2(wih23[3], d, aB23);
        }

        // ---- recurrent projection: exchange h within 8-lane group ----
#pragma unroll
        for (int k = 0; k < HDIM; ++k) {
            const u64 hdA = dup2(__shfl_sync(0xffffffffu, hA, k, 8));
            const u64 hdB = dup2(__shfl_sync(0xffffffffu, hB, k, 8));
            aA01 = fma2(whh01[k], hdA, aA01);
            aA23 = fma2(whh23[k], hdA, aA23);
            aB01 = fma2(whh01[k], hdB, aB01);
            aB23 = fma2(whh23[k], hdB, aB23);
        }

        // ---- activations + state update ----
        {
            const float2 g01 = unpack2(aA01);
            const float2 g23 = unpack2(aA23);
            const float ig = sig_fast(g01.x);
            const float fg = sig_fast(g01.y);
            const float gg = tanh_fast(g23.x);
            const float og = sig_fast(g23.y);
            cA = fmaf(fg, cA, ig * gg);
            hA = og * tanh_fast(cA);
        }
        {
            const float2 g01 = unpack2(aB01);
            const float2 g23 = unpack2(aB23);
            const float ig = sig_fast(g01.x);
            const float fg = sig_fast(g01.y);
            const float gg = tanh_fast(g23.x);
            const float og = sig_fast(g23.y);
            cB = fmaf(fg, cB, ig * gg);
            hB = og * tanh_fast(cB);
        }
    }

    // ---- FC head: out[b] = sum_j h_j * W_fc[j] + b_fc ----
    const float wj = __ldg(W_fc + j);
    const float bf = __ldg(b_fc);
    float vA = hA * wj;
    float vB = hB * wj;
    vA += __shfl_xor_sync(0xffffffffu, vA, 1, 8);
    vA += __shfl_xor_sync(0xffffffffu, vA, 2, 8);
    vA += __shfl_xor_sync(0xffffffffu, vA, 4, 8);
    vB += __shfl_xor_sync(0xffffffffu, vB, 1, 8);
    vB += __shfl_xor_sync(0xffffffffu, vB, 2, 8);
    vB += __shfl_xor_sync(0xffffffffu, vB, 4, 8);

    if (j == 0) {
        if (v0) out[b0] = vA + bf;
        if (v1) out[b1] = vB + bf;
    }
}

extern "C" void kernel_launch(void* const* d_in, const int* in_sizes, int n_in,
                              void* d_out, int out_size)
{
    const float* x    = (const float*)d_in[0];
    const float* W_ih = (const float*)d_in[1];
    const float* W_hh = (const float*)d_in[2];
    const float* b_ih = (const float*)d_in[3];
    const float* b_hh = (const float*)d_in[4];
    const float* W_fc = (const float*)d_in[5];
    const float* b_fc = (const float*)d_in[6];
    float* out = (float*)d_out;

    const int B = in_sizes[0] / (T_SEQ * IDIM);            // 8192 here
    const int half = (B + 1) >> 1;                         // batch groups (2 batches/thread)
    const int groups_per_block = 4;                        // 32 threads / 8 lanes
    const int grid = (half + groups_per_block - 1) / groups_per_block;

    lstm_fused_kernel<<<grid, 32>>>(x, W_ih, W_hh, b_ih, b_hh, W_fc, b_fc, out, B);
}

// round 3
// speedup vs baseline: 1.7776x; 1.2982x over previous
#include <cuda_runtime.h>

// LSTM: B x T x I -> last hidden -> FC.  I=4, H=8, O=1, T=512.
// Round-3 layout: ONE batch element per 8-lane group (65536 threads, 2048 warps)
// -> 3.46 warps/SMSP to hide the recurrence chain (round 2's 1024 warps were
//    latency-exposed: issue 26%).
// Kept from round 2: fma.rn.f32x2 gate-pair packing, tanh.approx.f32.
// New: sigmoid 0.5-scale folded into weight rows; even/odd split of the
//      recurrent accumulation (chain 32 -> ~20 cyc).

#define T_SEQ 512
#define IDIM  4
#define HDIM  8

typedef unsigned long long u64;

__device__ __forceinline__ u64 pack2(float a, float b) {
    u64 r; asm("mov.b64 %0,{%1,%2};" : "=l"(r) : "f"(a), "f"(b)); return r;
}
__device__ __forceinline__ u64 dup2(float a) {
    u64 r; asm("mov.b64 %0,{%1,%1};" : "=l"(r) : "f"(a)); return r;
}
__device__ __forceinline__ float2 unpack2(u64 v) {
    float2 r; asm("mov.b64 {%0,%1},%2;" : "=f"(r.x), "=f"(r.y) : "l"(v)); return r;
}
__device__ __forceinline__ u64 fma2(u64 a, u64 b, u64 c) {
    u64 d; asm("fma.rn.f32x2 %0,%1,%2,%3;" : "=l"(d) : "l"(a), "l"(b), "l"(c)); return d;
}
__device__ __forceinline__ u64 mul2(u64 a, u64 b) {
    u64 d; asm("mul.rn.f32x2 %0,%1,%2;" : "=l"(d) : "l"(a), "l"(b)); return d;
}
__device__ __forceinline__ u64 add2(u64 a, u64 b) {
    u64 d; asm("add.rn.f32x2 %0,%1,%2;" : "=l"(d) : "l"(a), "l"(b)); return d;
}
__device__ __forceinline__ float tanh_fast(float x) {
    float y; asm("tanh.approx.f32 %0,%1;" : "=f"(y) : "f"(x)); return y;
}

__global__ __launch_bounds__(64)
void lstm_fused_kernel(const float* __restrict__ x,
                       const float* __restrict__ W_ih,
                       const float* __restrict__ W_hh,
                       const float* __restrict__ b_ih,
                       const float* __restrict__ b_hh,
                       const float* __restrict__ W_fc,
                       const float* __restrict__ b_fc,
                       float* __restrict__ out,
                       int B)
{
    const int tid = threadIdx.x;
    const int j   = tid & 7;                        // hidden unit owned by this lane
    int b = blockIdx.x * 8 + (tid >> 3);            // batch element (8 groups / 64-thr block)
    const bool valid = (b < B);
    if (b >= B) b = B - 1;                          // clamp: keep warp converged

    // ---- per-lane weights in registers, packed over gate pairs (i,f) / (g,o).
    // Sigmoid gates (i,f,o) have their rows+bias pre-scaled by 0.5 so that
    // sigmoid(z) = 0.5*tanh(acc)+0.5 directly (acc = z/2). Gate g (tanh) unscaled.
    u64 wih01[IDIM], wih23[IDIM];
    u64 whh01[HDIM], whh23[HDIM];
    u64 bias01, bias23;
    {
        const int r0 = 0 * HDIM + j;   // i
        const int r1 = 1 * HDIM + j;   // f
        const int r2 = 2 * HDIM + j;   // g
        const int r3 = 3 * HDIM + j;   // o
#pragma unroll
        for (int m = 0; m < IDIM; ++m) {
            wih01[m] = pack2(0.5f * W_ih[r0 * IDIM + m], 0.5f * W_ih[r1 * IDIM + m]);
            wih23[m] = pack2(        W_ih[r2 * IDIM + m], 0.5f * W_ih[r3 * IDIM + m]);
        }
#pragma unroll
        for (int k = 0; k < HDIM; ++k) {
            whh01[k] = pack2(0.5f * W_hh[r0 * HDIM + k], 0.5f * W_hh[r1 * HDIM + k]);
            whh23[k] = pack2(        W_hh[r2 * HDIM + k], 0.5f * W_hh[r3 * HDIM + k]);
        }
        bias01 = pack2(0.5f * (b_ih[r0] + b_hh[r0]), 0.5f * (b_ih[r1] + b_hh[r1]));
        bias23 = pack2(        b_ih[r2] + b_hh[r2],  0.5f * (b_ih[r3] + b_hh[r3]));
    }

    const float4* __restrict__ xp =
        reinterpret_cast<const float4*>(x) + (size_t)b * T_SEQ;

    float h = 0.0f, c = 0.0f;
    float4 xv = xp[0];                               // prefetch t=0

#pragma unroll 2
    for (int t = 0; t < T_SEQ; ++t) {
        const float4 xc = xv;
        xv = xp[(t + 1) & (T_SEQ - 1)];              // prefetch next (wraps harmlessly)

        // ---- input projection + bias (h-independent; overlaps prev chain) ----
        const u64 d0 = dup2(xc.x), d1 = dup2(xc.y), d2 = dup2(xc.z), d3 = dup2(xc.w);
        u64 p01 = fma2(wih01[0], d0, bias01);
        u64 p23 = fma2(wih23[0], d0, bias23);
        p01 = fma2(wih01[1], d1, p01);  p23 = fma2(wih23[1], d1, p23);
        p01 = fma2(wih01[2], d2, p01);  p23 = fma2(wih23[2], d2, p23);
        p01 = fma2(wih01[3], d3, p01);  p23 = fma2(wih23[3], d3, p23);

        // ---- broadcast h within the 8-lane group ----
        const u64 h0 = dup2(__shfl_sync(0xffffffffu, h, 0, 8));
        const u64 h1 = dup2(__shfl_sync(0xffffffffu, h, 1, 8));
        const u64 h2 = dup2(__shfl_sync(0xffffffffu, h, 2, 8));
        const u64 h3 = dup2(__shfl_sync(0xffffffffu, h, 3, 8));
        const u64 h4 = dup2(__shfl_sync(0xffffffffu, h, 4, 8));
        const u64 h5 = dup2(__shfl_sync(0xffffffffu, h, 5, 8));
        const u64 h6 = dup2(__shfl_sync(0xffffffffu, h, 6, 8));
        const u64 h7 = dup2(__shfl_sync(0xffffffffu, h, 7, 8));

        // ---- recurrent projection, even/odd split for shorter chain ----
        p01 = fma2(whh01[0], h0, p01);  p23 = fma2(whh23[0], h0, p23);
        u64 q01 = mul2(whh01[4], h4);
        u64 q23 = mul2(whh23[4], h4);
        p01 = fma2(whh01[1], h1, p01);  p23 = fma2(whh23[1], h1, p23);
        q01 = fma2(whh01[5], h5, q01);  q23 = fma2(whh23[5], h5, q23);
        p01 = fma2(whh01[2], h2, p01);  p23 = fma2(whh23[2], h2, p23);
        q01 = fma2(whh01[6], h6, q01);  q23 = fma2(whh23[6], h6, q23);
        p01 = fma2(whh01[3], h3, p01);  p23 = fma2(whh23[3], h3, p23);
        q01 = fma2(whh01[7], h7, q01);  q23 = fma2(whh23[7], h7, q23);
        const u64 a01 = add2(p01, q01);
        const u64 a23 = add2(p23, q23);

        // ---- activations + state update ----
        const float2 g01 = unpack2(a01);   // (i/2, f/2)
        const float2 g23 = unpack2(a23);   // (g,   o/2)
        const float ig = fmaf(0.5f, tanh_fast(g01.x), 0.5f);
        const float fg = fmaf(0.5f, tanh_fast(g01.y), 0.5f);
        const float gg = tanh_fast(g23.x);
        const float og = fmaf(0.5f, tanh_fast(g23.y), 0.5f);
        c = fmaf(fg, c, ig * gg);
        h = og * tanh_fast(c);
    }

    // ---- FC head: out[b] = sum_j h_j * W_fc[j] + b_fc ----
    float v = h * __ldg(W_fc + j);
    v += __shfl_xor_sync(0xffffffffu, v, 1, 8);
    v += __shfl_xor_sync(0xffffffffu, v, 2, 8);
    v += __shfl_xor_sync(0xffffffffu, v, 4, 8);

    if (valid && j == 0) out[b] = v + __ldg(b_fc);
}

extern "C" void kernel_launch(void* const* d_in, const int* in_sizes, int n_in,
                              void* d_out, int out_size)
{
    const float* x    = (const float*)d_in[0];
    const float* W_ih = (const float*)d_in[1];
    const float* W_hh = (const float*)d_in[2];
    const float* b_ih = (const float*)d_in[3];
    const float* b_hh = (const float*)d_in[4];
    const float* W_fc = (const float*)d_in[5];
    const float* b_fc = (const float*)d_in[6];
    float* out = (float*)d_out;

    const int B = in_sizes[0] / (T_SEQ * IDIM);     // 8192 here
    const int groups_per_block = 8;                 // 64 threads / 8 lanes
    const int grid = (B + groups_per_block - 1) / groups_per_block;

    lstm_fused_kernel<<<grid, 64>>>(x, W_ih, W_hh, b_ih, b_hh, W_fc, b_fc, out, B);
}

// round 4
// speedup vs baseline: 1.9483x; 1.0961x over previous
#include <cuda_runtime.h>

// LSTM: B x T x I -> last hidden -> FC.  I=4, H=8, O=1, T=512.
// Round-4: identical math/layout to round 3 (8 lanes/batch, f32x2 gate pairs,
// tanh.approx, folded 0.5 scales), ONE change: the time loop is unrolled x4
// with a rolling 4-entry float4 buffer so x[t] loads are prefetched 4 steps
// (~550 cyc) ahead -> covers the DRAM-miss latency that round 3 exposed every
// step (x streams 64MB; every load is a cold miss, ~400+ cyc, pipeline was
// only 1 step deep).

#define T_SEQ 512
#define IDIM  4
#define HDIM  8

typedef unsigned long long u64;

__device__ __forceinline__ u64 pack2(float a, float b) {
    u64 r; asm("mov.b64 %0,{%1,%2};" : "=l"(r) : "f"(a), "f"(b)); return r;
}
__device__ __forceinline__ u64 dup2(float a) {
    u64 r; asm("mov.b64 %0,{%1,%1};" : "=l"(r) : "f"(a)); return r;
}
__device__ __forceinline__ float2 unpack2(u64 v) {
    float2 r; asm("mov.b64 {%0,%1},%2;" : "=f"(r.x), "=f"(r.y) : "l"(v)); return r;
}
__device__ __forceinline__ u64 fma2(u64 a, u64 b, u64 c) {
    u64 d; asm("fma.rn.f32x2 %0,%1,%2,%3;" : "=l"(d) : "l"(a), "l"(b), "l"(c)); return d;
}
__device__ __forceinline__ u64 mul2(u64 a, u64 b) {
    u64 d; asm("mul.rn.f32x2 %0,%1,%2;" : "=l"(d) : "l"(a), "l"(b)); return d;
}
__device__ __forceinline__ u64 add2(u64 a, u64 b) {
    u64 d; asm("add.rn.f32x2 %0,%1,%2;" : "=l"(d) : "l"(a), "l"(b)); return d;
}
__device__ __forceinline__ float tanh_fast(float x) {
    float y; asm("tanh.approx.f32 %0,%1;" : "=f"(y) : "f"(x)); return y;
}

struct LaneW {
    u64 wih01[IDIM], wih23[IDIM];
    u64 whh01[HDIM], whh23[HDIM];
    u64 bias01, bias23;
};

// One LSTM timestep for this lane's unit. h,c updated in place.
__device__ __forceinline__ void lstm_step(const LaneW& W, float4 xc,
                                          float& h, float& c)
{
    const u64 d0 = dup2(xc.x), d1 = dup2(xc.y), d2 = dup2(xc.z), d3 = dup2(xc.w);
    u64 p01 = fma2(W.wih01[0], d0, W.bias01);
    u64 p23 = fma2(W.wih23[0], d0, W.bias23);
    p01 = fma2(W.wih01[1], d1, p01);  p23 = fma2(W.wih23[1], d1, p23);
    p01 = fma2(W.wih01[2], d2, p01);  p23 = fma2(W.wih23[2], d2, p23);
    p01 = fma2(W.wih01[3], d3, p01);  p23 = fma2(W.wih23[3], d3, p23);

    const u64 h0 = dup2(__shfl_sync(0xffffffffu, h, 0, 8));
    const u64 h1 = dup2(__shfl_sync(0xffffffffu, h, 1, 8));
    const u64 h2 = dup2(__shfl_sync(0xffffffffu, h, 2, 8));
    const u64 h3 = dup2(__shfl_sync(0xffffffffu, h, 3, 8));
    const u64 h4 = dup2(__shfl_sync(0xffffffffu, h, 4, 8));
    const u64 h5 = dup2(__shfl_sync(0xffffffffu, h, 5, 8));
    const u64 h6 = dup2(__shfl_sync(0xffffffffu, h, 6, 8));
    const u64 h7 = dup2(__shfl_sync(0xffffffffu, h, 7, 8));

    p01 = fma2(W.whh01[0], h0, p01);  p23 = fma2(W.whh23[0], h0, p23);
    u64 q01 = mul2(W.whh01[4], h4);
    u64 q23 = mul2(W.whh23[4], h4);
    p01 = fma2(W.whh01[1], h1, p01);  p23 = fma2(W.whh23[1], h1, p23);
    q01 = fma2(W.whh01[5], h5, q01);  q23 = fma2(W.whh23[5], h5, q23);
    p01 = fma2(W.whh01[2], h2, p01);  p23 = fma2(W.whh23[2], h2, p23);
    q01 = fma2(W.whh01[6], h6, q01);  q23 = fma2(W.whh23[6], h6, q23);
    p01 = fma2(W.whh01[3], h3, p01);  p23 = fma2(W.whh23[3], h3, p23);
    q01 = fma2(W.whh01[7], h7, q01);  q23 = fma2(W.whh23[7], h7, q23);
    const u64 a01 = add2(p01, q01);
    const u64 a23 = add2(p23, q23);

    const float2 g01 = unpack2(a01);   // (i/2, f/2)
    const float2 g23 = unpack2(a23);   // (g,   o/2)
    const float ig = fmaf(0.5f, tanh_fast(g01.x), 0.5f);
    const float fg = fmaf(0.5f, tanh_fast(g01.y), 0.5f);
    const float gg = tanh_fast(g23.x);
    const float og = fmaf(0.5f, tanh_fast(g23.y), 0.5f);
    c = fmaf(fg, c, ig * gg);
    h = og * tanh_fast(c);
}

__global__ __launch_bounds__(64)
void lstm_fused_kernel(const float* __restrict__ x,
                       const float* __restrict__ W_ih,
                       const float* __restrict__ W_hh,
                       const float* __restrict__ b_ih,
                       const float* __restrict__ b_hh,
                       const float* __restrict__ W_fc,
                       const float* __restrict__ b_fc,
                       float* __restrict__ out,
                       int B)
{
    const int tid = threadIdx.x;
    const int j   = tid & 7;                        // hidden unit owned by this lane
    int b = blockIdx.x * 8 + (tid >> 3);            // batch element
    const bool valid = (b < B);
    if (b >= B) b = B - 1;                          // clamp: keep warp converged

    // ---- per-lane weights, packed over gate pairs (i,f)/(g,o); sigmoid gates
    // (i,f,o) pre-scaled by 0.5 so sigmoid(z) = 0.5*tanh(acc)+0.5 directly.
    LaneW W;
    {
        const int r0 = 0 * HDIM + j;   // i
        const int r1 = 1 * HDIM + j;   // f
        const int r2 = 2 * HDIM + j;   // g
        const int r3 = 3 * HDIM + j;   // o
#pragma unroll
        for (int m = 0; m < IDIM; ++m) {
            W.wih01[m] = pack2(0.5f * W_ih[r0 * IDIM + m], 0.5f * W_ih[r1 * IDIM + m]);
            W.wih23[m] = pack2(        W_ih[r2 * IDIM + m], 0.5f * W_ih[r3 * IDIM + m]);
        }
#pragma unroll
        for (int k = 0; k < HDIM; ++k) {
            W.whh01[k] = pack2(0.5f * W_hh[r0 * HDIM + k], 0.5f * W_hh[r1 * HDIM + k]);
            W.whh23[k] = pack2(        W_hh[r2 * HDIM + k], 0.5f * W_hh[r3 * HDIM + k]);
        }
        W.bias01 = pack2(0.5f * (b_ih[r0] + b_hh[r0]), 0.5f * (b_ih[r1] + b_hh[r1]));
        W.bias23 = pack2(        b_ih[r2] + b_hh[r2],  0.5f * (b_ih[r3] + b_hh[r3]));
    }

    const float4* __restrict__ xp =
        reinterpret_cast<const float4*>(x) + (size_t)b * T_SEQ;

    float h = 0.0f, c = 0.0f;

    // ---- rolling 4-step prefetch buffer: loads run ~4 steps (~550 cyc) ahead
    float4 buf0 = xp[0], buf1 = xp[1], buf2 = xp[2], buf3 = xp[3];

#pragma unroll 1
    for (int t0 = 0; t0 < T_SEQ; t0 += 4) {
        // issue next group's 4 independent loads first (MLP=4, covers DRAM miss)
        const int tn = (t0 + 4) & (T_SEQ - 1);      // wraps to 0 on last iter (harmless)
        const float4 n0 = xp[tn + 0];
        const float4 n1 = xp[tn + 1];
        const float4 n2 = xp[tn + 2];
        const float4 n3 = xp[tn + 3];

        lstm_step(W, buf0, h, c);
        lstm_step(W, buf1, h, c);
        lstm_step(W, buf2, h, c);
        lstm_step(W, buf3, h, c);

        buf0 = n0; buf1 = n1; buf2 = n2; buf3 = n3;
    }

    // ---- FC head: out[b] = sum_j h_j * W_fc[j] + b_fc ----
    float v = h * __ldg(W_fc + j);
    v += __shfl_xor_sync(0xffffffffu, v, 1, 8);
    v += __shfl_xor_sync(0xffffffffu, v, 2, 8);
    v += __shfl_xor_sync(0xffffffffu, v, 4, 8);

    if (valid && j == 0) out[b] = v + __ldg(b_fc);
}

extern "C" void kernel_launch(void* const* d_in, const int* in_sizes, int n_in,
                              void* d_out, int out_size)
{
    const float* x    = (const float*)d_in[0];
    const float* W_ih = (const float*)d_in[1];
    const float* W_hh = (const float*)d_in[2];
    const float* b_ih = (const float*)d_in[3];
    const float* b_hh = (const float*)d_in[4];
    const float* W_fc = (const float*)d_in[5];
    const float* b_fc = (const float*)d_in[6];
    float* out = (float*)d_out;

    const int B = in_sizes[0] / (T_SEQ * IDIM);     // 8192 here
    const int groups_per_block = 8;                 // 64 threads / 8 lanes
    const int grid = (B + groups_per_block - 1) / groups_per_block;

    lstm_fused_kernel<<<grid, 64>>>(x, W_ih, W_hh, b_ih, b_hh, W_fc, b_fc, out, B);
}